// round 15
// baseline (speedup 1.0000x reference)
#include <cuda_runtime.h>
#include <cuda_bf16.h>
#include <mma.h>
#include <math.h>
#include <stdint.h>

using namespace nvcuda;

#define HD    1024
#define AD    256
#define ID    2048
#define NE    8
#define NTOK  4096
#define NSLOT 8192
#define R1N   4096
#define XTK   1280   // H + A

// ================= device-global scratch (fp32 only) =================
__device__ __align__(1024) float g_rh1[(size_t)NTOK * R1N];
__device__ __align__(1024) float g_rh2[(size_t)NTOK * HD];
__device__ __align__(1024) float g_h1a[(size_t)NSLOT * ID];
__device__ __align__(1024) float g_hmid[(size_t)NSLOT * HD];
__device__ __align__(1024) float g_h1b[(size_t)NSLOT * ID];
__device__ __align__(1024) float g_y[(size_t)NSLOT * HD];
__device__ __align__(1024) float g_ap[NE * HD];
__device__ __align__(1024) float g_c1[NE * ID];
__device__ float g_probs[NTOK * NE];
__device__ float g_ent[NTOK];
__device__ int   g_topk[NTOK * 2];
__device__ int   g_slot_of_tok[NTOK * 2];
__device__ int   g_tok_of_slot[NSLOT];
__device__ int   g_expert_of_slot[NSLOT];
__device__ int   g_cnt[NE];
__device__ int   g_off[NE];
__device__ int   g_cursor[NE];

__device__ __forceinline__ void split2(float v, __nv_bfloat16& h, __nv_bfloat16& l) {
  h = __float2bfloat16(v);
  l = __float2bfloat16(v - __bfloat162float(h));
}

// ================= small kernels =================
__global__ void reset_k() {
  int i = threadIdx.x;
  if (i < NE) { g_cnt[i] = 0; g_cursor[i] = 0; }
}

__global__ void ap_k(const float* __restrict__ ae, const float* __restrict__ apw,
                     const float* __restrict__ apb) {
  int idx = blockIdx.x * blockDim.x + threadIdx.x;
  if (idx >= NE * HD) return;
  int e = idx >> 10;
  const float* a = ae + e * AD;
  const float* w = apw + (size_t)idx * AD;
  float s = 0.f;
#pragma unroll 4
  for (int d = 0; d < AD; d += 4) {
    float4 av = *(const float4*)(a + d);
    float4 wv = *(const float4*)(w + d);
    s += av.x * wv.x + av.y * wv.y + av.z * wv.z + av.w * wv.w;
  }
  g_ap[idx] = s + apb[idx];
}

__global__ void c1_k(const float* __restrict__ gw1, const float* __restrict__ gb1) {
  int idx = blockIdx.x * blockDim.x + threadIdx.x;
  if (idx >= NE * ID) return;
  int e = idx / ID;
  const float* w = gw1 + (size_t)idx * (2 * HD) + HD;
  const float* a = g_ap + e * HD;
  float s = 0.f;
#pragma unroll 4
  for (int d = 0; d < HD; d += 4) {
    float4 wv = *(const float4*)(w + d);
    float4 av = *(const float4*)(a + d);
    s += wv.x * av.x + wv.y * av.y + wv.z * av.z + wv.w * av.w;
  }
  g_c1[idx] = s + gb1[idx];
}

// ============ wmma bf16x3 GEMM, 128x256 tile, in-kernel conversion ============
// MODE 0: concat(x,te) @ r_in^T + b -> relu -> g_rh1      (dense)
// MODE 1: rh1 @ r_mid^T + b -> relu -> g_rh2              (dense)
// MODE 2: x[tok] @ gw1[:, :H]^T + c1 -> relu -> g_h1a     (routed)
// MODE 3: h1a @ gw2^T + gb2 -> sigmoid mix -> g_hmid      (routed)
// MODE 4: hmid @ fw1^T + fb1 -> relu -> g_h1b             (routed)
// MODE 5: h1b @ fw2^T + fb2 + x -> g_y                    (routed)
#define PITCH  40
#define AHO    0
#define ALO    (128 * PITCH)
#define BHO    (256 * PITCH)
#define BLO    (512 * PITCH)
#define SSE    (768 * PITCH)            // stage elems = 61440 B
#define CP2    132
#define SMEM_DYN (2 * SSE * 2 + 1024)

template <int MODE>
__global__ void __launch_bounds__(256, 1)
mgemm_k(const float* __restrict__ W, const float* __restrict__ Bias,
        const float* __restrict__ xin, const float* __restrict__ tein,
        long wstride) {
  constexpr int N = (MODE == 0) ? R1N : (MODE == 2 || MODE == 4) ? ID : HD;
  constexpr int K = (MODE == 0) ? XTK : (MODE == 1) ? R1N
                   : (MODE == 3 || MODE == 5) ? ID : HD;
  constexpr int KT = K >> 5;

  const int e = (MODE >= 2) ? blockIdx.z : 0;
  const int mcount = (MODE >= 2) ? g_cnt[e] : NTOK;
  const int moff = (MODE >= 2) ? g_off[e] : 0;
  const int m0 = blockIdx.y * 128;
  if (m0 >= mcount) return;
  const int n0 = blockIdx.x * 256;

  extern __shared__ char dsm[];
  char* dynp = (char*)(((uintptr_t)dsm + 1023) & ~(uintptr_t)1023);
  __nv_bfloat16* smb = (__nv_bfloat16*)dynp;
  float* csm = (float*)dynp;

  const int tid = threadIdx.x;
  const int wid = tid >> 5;
  const int lrow = tid >> 1;
  const int colb = (tid & 1) << 4;

  // ---- fp32 global row pointers ----
  int am = m0 + lrow;
  if (am >= mcount) am = mcount - 1;
  const float* arow;
  const float* tadj = nullptr;
  if (MODE == 0) {
    arow = xin + (size_t)am * HD;
    tadj = tein + (size_t)am * AD - HD;
  } else if (MODE == 1) {
    arow = g_rh1 + (size_t)am * R1N;
  } else {
    const int aslot = moff + am;
    if (MODE == 2)      arow = xin + (size_t)g_tok_of_slot[aslot] * HD;
    else if (MODE == 3) arow = g_h1a + (size_t)aslot * ID;
    else if (MODE == 4) arow = g_hmid + (size_t)aslot * HD;
    else                arow = g_h1b + (size_t)aslot * ID;
  }
  const float* brow0 = W + ((size_t)e * N + n0 + lrow) * (size_t)wstride;
  const float* brow1 = brow0 + (size_t)128 * wstride;

  float4 ar[4], br0[4], br1[4];

#define LOADR(kbase) do { \
  int k0_ = (kbase) + colb; \
  const float* ab_ = (MODE == 0 && k0_ >= HD) ? tadj : arow; \
  _Pragma("unroll") \
  for (int q = 0; q < 4; q++) { \
    ar[q]  = *(const float4*)(ab_   + k0_ + q * 4); \
    br0[q] = *(const float4*)(brow0 + k0_ + q * 4); \
    br1[q] = *(const float4*)(brow1 + k0_ + q * 4); \
  } \
} while (0)

#define SPLIT16(srcp, dsth, dstl) do { \
  const float* f_ = (const float*)(srcp); \
  _Pragma("unroll") \
  for (int i = 0; i < 16; i += 2) { \
    __nv_bfloat16 h0, l0, h1, l1; \
    split2(f_[i], h0, l0); split2(f_[i + 1], h1, l1); \
    *(__nv_bfloat162*)((dsth) + i) = __nv_bfloat162(h0, h1); \
    *(__nv_bfloat162*)((dstl) + i) = __nv_bfloat162(l0, l1); \
  } \
} while (0)

#define STORES(stage) do { \
  __nv_bfloat16* s_ = smb + (stage) * SSE; \
  __nv_bfloat16* as_ = s_ + lrow * PITCH + colb; \
  SPLIT16(ar, as_ + AHO, as_ + ALO); \
  __nv_bfloat16* b0_ = s_ + BHO + lrow * PITCH + colb; \
  SPLIT16(br0, b0_, b0_ + (BLO - BHO)); \
  __nv_bfloat16* b1_ = s_ + BHO + (128 + lrow) * PITCH + colb; \
  SPLIT16(br1, b1_, b1_ + (BLO - BHO)); \
} while (0)

  // ---- wmma tiling: 8 warps = 2(m) x 4(n); warp tile 64m x 64n ----
  const int wm = wid & 1;
  const int wn = wid >> 1;

  wmma::fragment<wmma::accumulator, 16, 16, 16, float> cf[4][4];
#pragma unroll
  for (int mt = 0; mt < 4; mt++)
#pragma unroll
    for (int nt = 0; nt < 4; nt++) wmma::fill_fragment(cf[mt][nt], 0.f);

  LOADR(0);
  STORES(0);
  __syncthreads();

  for (int c = 0; c < KT; c++) {
    // Early prefetch + convert + store for the NEXT stage: frees ar/br
    // registers before the MMA section (they were live across it before,
    // pushing regs to the 255 cap and spilling). Safe: buffer (c+1)&1 was
    // last read in iteration c-1, separated by that iteration's sync.
    if (c + 1 < KT) {
      LOADR((c + 1) << 5);
      STORES((c + 1) & 1);
    }
    const __nv_bfloat16* sb = smb + (c & 1) * SSE;
#pragma unroll
    for (int ks = 0; ks < 2; ks++) {
      wmma::fragment<wmma::matrix_b, 16, 16, 16, __nv_bfloat16, wmma::col_major> bh[4], bl[4];
#pragma unroll
      for (int nt = 0; nt < 4; nt++) {
        const int bo = (wn * 64 + nt * 16) * PITCH + ks * 16;
        wmma::load_matrix_sync(bh[nt], sb + BHO + bo, PITCH);
        wmma::load_matrix_sync(bl[nt], sb + BLO + bo, PITCH);
      }
#pragma unroll
      for (int mt = 0; mt < 4; mt++) {
        const int ao = (wm * 64 + mt * 16) * PITCH + ks * 16;
        wmma::fragment<wmma::matrix_a, 16, 16, 16, __nv_bfloat16, wmma::row_major> ah, al;
        wmma::load_matrix_sync(ah, sb + AHO + ao, PITCH);
        wmma::load_matrix_sync(al, sb + ALO + ao, PITCH);
#pragma unroll
        for (int nt = 0; nt < 4; nt++) {
          wmma::mma_sync(cf[mt][nt], ah, bh[nt], cf[mt][nt]);
          wmma::mma_sync(cf[mt][nt], al, bh[nt], cf[mt][nt]);
          wmma::mma_sync(cf[mt][nt], ah, bl[nt], cf[mt][nt]);
        }
      }
    }
    __syncthreads();
  }

  // ---- two-pass epilogue: 128 columns at a time through fp32 smem ----
  const float* bias;
  if (MODE <= 1)      bias = Bias;
  else if (MODE == 2) bias = g_c1 + e * ID;
  else if (MODE == 3) bias = Bias + (size_t)e * HD;
  else if (MODE == 4) bias = Bias + (size_t)e * ID;
  else                bias = Bias + (size_t)e * HD;

  const int r = tid >> 1;
  const int ch = tid & 1;
  const int mi = m0 + r;
  const bool valid = (mi < mcount);
  const int slot = moff + (valid ? mi : 0);
  const int tok = (MODE >= 2) ? g_tok_of_slot[slot] : mi;
  const long orow = (MODE >= 2) ? (long)slot : (long)mi;

#pragma unroll
  for (int hf = 0; hf < 2; hf++) {
    if ((wn >> 1) == hf) {
      const int wnl = wn & 1;
#pragma unroll
      for (int mt = 0; mt < 4; mt++)
#pragma unroll
        for (int nt = 0; nt < 4; nt++)
          wmma::store_matrix_sync(csm + (wm * 64 + mt * 16) * CP2 + wnl * 64 + nt * 16,
                                  cf[mt][nt], CP2, wmma::mem_row_major);
    }
    __syncthreads();
    if (valid) {
      const float* crow = csm + r * CP2 + ch * 64;
      const int nb = n0 + hf * 128 + ch * 64;
#pragma unroll
      for (int j = 0; j < 64; j++) {
        const int n = nb + j;
        float v = crow[j] + bias[n];
        if (MODE == 0) {
          g_rh1[orow * R1N + n] = fmaxf(v, 0.f);
        } else if (MODE == 1) {
          g_rh2[orow * HD + n] = fmaxf(v, 0.f);
        } else if (MODE == 2) {
          g_h1a[orow * ID + n] = fmaxf(v, 0.f);
        } else if (MODE == 3) {
          float g = 1.f / (1.f + expf(-v));
          float xv = xin[(size_t)tok * HD + n];
          float apv = g_ap[e * HD + n];
          g_hmid[orow * HD + n] = xv * g + apv * (1.f - g);
        } else if (MODE == 4) {
          g_h1b[orow * ID + n] = fmaxf(v, 0.f);
        } else {
          g_y[orow * HD + n] = v + xin[(size_t)tok * HD + n];
        }
      }
    }
    if (hf == 0) __syncthreads();
  }
}

// ================= router head / routing / LN / combine / loss =================
__global__ void router_head_k(const float* __restrict__ te,
                              const float* __restrict__ r_attr,
                              const float* __restrict__ r_w,
                              const float* __restrict__ r_b) {
  int t = blockIdx.x;
  int tid = threadIdx.x;
  const float* hrow = g_rh2 + (size_t)t * HD;
  float pe[NE];
#pragma unroll
  for (int e = 0; e < NE; e++) pe[e] = 0.f;
  for (int k = tid; k < HD; k += 256) {
    float hv = hrow[k];
#pragma unroll
    for (int e = 0; e < NE; e++) pe[e] = fmaf(hv, r_w[e * HD + k], pe[e]);
  }
#pragma unroll
  for (int e = 0; e < NE; e++)
    for (int o = 16; o > 0; o >>= 1) pe[e] += __shfl_xor_sync(0xffffffffu, pe[e], o);
  __shared__ float sw[NE][8];
  int w = tid >> 5;
  if ((tid & 31) == 0)
#pragma unroll
    for (int e = 0; e < NE; e++) sw[e][w] = pe[e];
  __syncthreads();
  if (tid == 0) {
    float lg[NE];
    float mx = -1e30f;
    for (int e = 0; e < NE; e++) {
      float s = 0.f;
      for (int i = 0; i < 8; i++) s += sw[e][i];
      s += r_b[e];
      lg[e] = s;
      if (s > mx) mx = s;
    }
    float se = 0.f;
    for (int e = 0; e < NE; e++) { lg[e] = expf(lg[e] - mx); se += lg[e]; }
    float inv = 1.f / se;

    float attr[NE];
    for (int e = 0; e < NE; e++) attr[e] = 0.f;
    const float* tr = te + (size_t)t * AD;
    for (int n = 0; n < 4; n++) {
      float sc[NE];
      for (int e = 0; e < NE; e++) sc[e] = 0.f;
      for (int d = 0; d < 64; d++) {
        float tv = tr[n * 64 + d];
#pragma unroll
        for (int e = 0; e < NE; e++) sc[e] = fmaf(tv, r_attr[d * NE + e], sc[e]);
      }
      float m2 = -1e30f;
      for (int e = 0; e < NE; e++) if (sc[e] > m2) m2 = sc[e];
      float ss = 0.f;
      for (int e = 0; e < NE; e++) { sc[e] = expf(sc[e] - m2); ss += sc[e]; }
      float rr = 0.25f / ss;
      for (int e = 0; e < NE; e++) attr[e] += sc[e] * rr;
    }

    float p[NE];
    for (int e = 0; e < NE; e++) p[e] = lg[e] * inv * attr[e];
    int i0 = 0;
    for (int e = 1; e < NE; e++) if (p[e] > p[i0]) i0 = e;
    int i1 = (i0 == 0) ? 1 : 0;
    for (int e = 0; e < NE; e++) if (e != i0 && p[e] > p[i1]) i1 = e;

    for (int e = 0; e < NE; e++)
      g_probs[t * NE + e] = (e == i0 || e == i1) ? p[e] : 0.f;
    float p0 = p[i0], p1 = p[i1];
    g_ent[t] = p0 * logf(p0 + 1e-8f) + p1 * logf(p1 + 1e-8f);
    int elo = i0 < i1 ? i0 : i1;
    int ehi = i0 < i1 ? i1 : i0;
    g_topk[2 * t] = elo;
    g_topk[2 * t + 1] = ehi;
    atomicAdd(&g_cnt[elo], 1);
    atomicAdd(&g_cnt[ehi], 1);
  }
}

__global__ void offsets_k() {
  if (threadIdx.x == 0) {
    int o = 0;
    for (int e = 0; e < NE; e++) { g_off[e] = o; o += g_cnt[e]; }
  }
}

__global__ void assign_k() {
  int t = blockIdx.x * blockDim.x + threadIdx.x;
  if (t >= NTOK) return;
#pragma unroll
  for (int k = 0; k < 2; k++) {
    int e = g_topk[2 * t + k];
    int slot = g_off[e] + atomicAdd(&g_cursor[e], 1);
    g_tok_of_slot[slot] = t;
    g_expert_of_slot[slot] = e;
    g_slot_of_tok[2 * t + k] = slot;
  }
}

__global__ void ln_k(const float* __restrict__ lng, const float* __restrict__ lnb) {
  int s = blockIdx.x;
  int e = g_expert_of_slot[s];
  float* row = g_y + (size_t)s * HD;
  int tid = threadIdx.x;
  float4 v = *(const float4*)(row + tid * 4);
  float sum = v.x + v.y + v.z + v.w;
  float sq = v.x * v.x + v.y * v.y + v.z * v.z + v.w * v.w;
  for (int o = 16; o > 0; o >>= 1) {
    sum += __shfl_xor_sync(0xffffffffu, sum, o);
    sq += __shfl_xor_sync(0xffffffffu, sq, o);
  }
  __shared__ float s1[8], s2[8];
  int w = tid >> 5;
  if ((tid & 31) == 0) { s1[w] = sum; s2[w] = sq; }
  __syncthreads();
  float ts = 0.f, tq = 0.f;
#pragma unroll
  for (int i = 0; i < 8; i++) { ts += s1[i]; tq += s2[i]; }
  float mu = ts * (1.f / HD);
  float var = tq * (1.f / HD) - mu * mu;
  float rstd = rsqrtf(var + 1e-5f);
  const float4 g4 = *(const float4*)(lng + e * HD + tid * 4);
  const float4 b4 = *(const float4*)(lnb + e * HD + tid * 4);
  float4 o;
  o.x = (v.x - mu) * rstd * g4.x + b4.x;
  o.y = (v.y - mu) * rstd * g4.y + b4.y;
  o.z = (v.z - mu) * rstd * g4.z + b4.z;
  o.w = (v.w - mu) * rstd * g4.w + b4.w;
  *(float4*)(row + tid * 4) = o;
}

__global__ void combine_k(float* __restrict__ out) {
  int t = blockIdx.x;
  int tid = threadIdx.x;
  int s0 = g_slot_of_tok[2 * t], s1 = g_slot_of_tok[2 * t + 1];
  int e0 = g_topk[2 * t], e1 = g_topk[2 * t + 1];
  float p0 = g_probs[t * NE + e0], p1 = g_probs[t * NE + e1];
  const float4 y0 = *(const float4*)(g_y + (size_t)s0 * HD + tid * 4);
  const float4 y1 = *(const float4*)(g_y + (size_t)s1 * HD + tid * 4);
  float4 o;
  o.x = p0 * y0.x + p1 * y1.x;
  o.y = p0 * y0.y + p1 * y1.y;
  o.z = p0 * y0.z + p1 * y1.z;
  o.w = p0 * y0.w + p1 * y1.w;
  *(float4*)(out + (size_t)t * HD + tid * 4) = o;
}

__global__ void loss_k(float* __restrict__ out, int out_size) {
  __shared__ float red[256];
  float s = 0.f;
  for (int i = threadIdx.x; i < NTOK; i += 256) s += g_ent[i];
  red[threadIdx.x] = s;
  __syncthreads();
  for (int o = 128; o > 0; o >>= 1) {
    if (threadIdx.x < o) red[threadIdx.x] += red[threadIdx.x + o];
    __syncthreads();
  }
  if (threadIdx.x == 0) {
    float loss = -red[0] / (float)NTOK;
    for (int i = NTOK * HD; i < out_size; i++) out[i] = loss;
  }
}

// ================= launch =================
extern "C" void kernel_launch(void* const* d_in, const int* in_sizes, int n_in,
                              void* d_out, int out_size) {
  const float* x           = (const float*)d_in[0];
  const float* te          = (const float*)d_in[1];
  const float* attr_emb    = (const float*)d_in[2];
  const float* attr_proj_w = (const float*)d_in[3];
  const float* attr_proj_b = (const float*)d_in[4];
  const float* gate_w1     = (const float*)d_in[5];
  const float* gate_b1     = (const float*)d_in[6];
  const float* gate_w2     = (const float*)d_in[7];
  const float* gate_b2     = (const float*)d_in[8];
  const float* fc_w1       = (const float*)d_in[9];
  const float* fc_b1       = (const float*)d_in[10];
  const float* fc_w2       = (const float*)d_in[11];
  const float* fc_b2       = (const float*)d_in[12];
  const float* ln_g        = (const float*)d_in[13];
  const float* ln_b        = (const float*)d_in[14];
  const float* r_attr      = (const float*)d_in[15];
  const float* r_in_w      = (const float*)d_in[16];
  const float* r_in_b      = (const float*)d_in[17];
  const float* r_mid_w     = (const float*)d_in[18];
  const float* r_mid_b     = (const float*)d_in[19];
  const float* r_w         = (const float*)d_in[20];
  const float* r_b         = (const float*)d_in[21];
  float* out = (float*)d_out;

  cudaFuncSetAttribute(mgemm_k<0>, cudaFuncAttributeMaxDynamicSharedMemorySize, SMEM_DYN);
  cudaFuncSetAttribute(mgemm_k<1>, cudaFuncAttributeMaxDynamicSharedMemorySize, SMEM_DYN);
  cudaFuncSetAttribute(mgemm_k<2>, cudaFuncAttributeMaxDynamicSharedMemorySize, SMEM_DYN);
  cudaFuncSetAttribute(mgemm_k<3>, cudaFuncAttributeMaxDynamicSharedMemorySize, SMEM_DYN);
  cudaFuncSetAttribute(mgemm_k<4>, cudaFuncAttributeMaxDynamicSharedMemorySize, SMEM_DYN);
  cudaFuncSetAttribute(mgemm_k<5>, cudaFuncAttributeMaxDynamicSharedMemorySize, SMEM_DYN);

  reset_k<<<1, 32>>>();
  ap_k<<<(NE * HD + 255) / 256, 256>>>(attr_emb, attr_proj_w, attr_proj_b);
  c1_k<<<(NE * ID + 255) / 256, 256>>>(gate_w1, gate_b1);

  // router MLP — bf16x3 wmma (head / top-k stays exact fp32)
  mgemm_k<0><<<dim3(R1N / 256, NTOK / 128, 1), 256, SMEM_DYN>>>(r_in_w, r_in_b, x, te, XTK);
  mgemm_k<1><<<dim3(HD / 256, NTOK / 128, 1), 256, SMEM_DYN>>>(r_mid_w, r_mid_b, nullptr, nullptr, R1N);
  router_head_k<<<NTOK, 256>>>(te, r_attr, r_w, r_b);
  offsets_k<<<1, 32>>>();
  assign_k<<<NTOK / 256, 256>>>();

  // expert FFNs — bf16x3 wmma, 128x256 tiles
  mgemm_k<2><<<dim3(ID / 256, NTOK / 128, NE), 256, SMEM_DYN>>>(gate_w1, gate_b1, x, nullptr, 2 * HD);
  mgemm_k<3><<<dim3(HD / 256, NTOK / 128, NE), 256, SMEM_DYN>>>(gate_w2, gate_b2, x, nullptr, ID);
  mgemm_k<4><<<dim3(ID / 256, NTOK / 128, NE), 256, SMEM_DYN>>>(fc_w1, fc_b1, x, nullptr, HD);
  mgemm_k<5><<<dim3(HD / 256, NTOK / 128, NE), 256, SMEM_DYN>>>(fc_w2, fc_b2, x, nullptr, ID);

  ln_k<<<NSLOT, 256>>>(ln_g, ln_b);
  combine_k<<<NTOK, 256>>>(out);
  loss_k<<<1, 256>>>(out, out_size);
}

// round 16
// speedup vs baseline: 1.1306x; 1.1306x over previous
#include <cuda_runtime.h>
#include <cuda_bf16.h>
#include <mma.h>
#include <math.h>
#include <stdint.h>

using namespace nvcuda;

#define HD    1024
#define AD    256
#define ID    2048
#define NE    8
#define NTOK  4096
#define NSLOT 8192
#define R1N   4096
#define XTK   1280   // H + A

// ================= device-global scratch (fp32 only) =================
__device__ __align__(1024) float g_rh1[(size_t)NTOK * R1N];
__device__ __align__(1024) float g_rh2[(size_t)NTOK * HD];
__device__ __align__(1024) float g_h1a[(size_t)NSLOT * ID];
__device__ __align__(1024) float g_hmid[(size_t)NSLOT * HD];
__device__ __align__(1024) float g_h1b[(size_t)NSLOT * ID];
__device__ __align__(1024) float g_y[(size_t)NSLOT * HD];
__device__ __align__(1024) float g_ap[NE * HD];
__device__ __align__(1024) float g_c1[NE * ID];
__device__ float g_probs[NTOK * NE];
__device__ float g_ent[NTOK];
__device__ int   g_topk[NTOK * 2];
__device__ int   g_slot_of_tok[NTOK * 2];
__device__ int   g_tok_of_slot[NSLOT];
__device__ int   g_expert_of_slot[NSLOT];
__device__ int   g_cnt[NE];
__device__ int   g_off[NE];
__device__ int   g_cursor[NE];

__device__ __forceinline__ void split2(float v, __nv_bfloat16& h, __nv_bfloat16& l) {
  h = __float2bfloat16(v);
  l = __float2bfloat16(v - __bfloat162float(h));
}

// ================= small kernels =================
__global__ void reset_k() {
  int i = threadIdx.x;
  if (i < NE) { g_cnt[i] = 0; g_cursor[i] = 0; }
}

__global__ void ap_k(const float* __restrict__ ae, const float* __restrict__ apw,
                     const float* __restrict__ apb) {
  int idx = blockIdx.x * blockDim.x + threadIdx.x;
  if (idx >= NE * HD) return;
  int e = idx >> 10;
  const float* a = ae + e * AD;
  const float* w = apw + (size_t)idx * AD;
  float s = 0.f;
#pragma unroll 4
  for (int d = 0; d < AD; d += 4) {
    float4 av = *(const float4*)(a + d);
    float4 wv = *(const float4*)(w + d);
    s += av.x * wv.x + av.y * wv.y + av.z * wv.z + av.w * wv.w;
  }
  g_ap[idx] = s + apb[idx];
}

__global__ void c1_k(const float* __restrict__ gw1, const float* __restrict__ gb1) {
  int idx = blockIdx.x * blockDim.x + threadIdx.x;
  if (idx >= NE * ID) return;
  int e = idx / ID;
  const float* w = gw1 + (size_t)idx * (2 * HD) + HD;
  const float* a = g_ap + e * HD;
  float s = 0.f;
#pragma unroll 4
  for (int d = 0; d < HD; d += 4) {
    float4 wv = *(const float4*)(w + d);
    float4 av = *(const float4*)(a + d);
    s += wv.x * av.x + wv.y * av.y + wv.z * av.z + wv.w * av.w;
  }
  g_c1[idx] = s + gb1[idx];
}

// ============ wmma bf16x3 GEMM, 128x256 tile, in-kernel conversion ============
// MODE 0: concat(x,te) @ r_in^T + b -> relu -> g_rh1      (dense)
// MODE 1: rh1 @ r_mid^T + b -> relu -> g_rh2              (dense)
// MODE 2: x[tok] @ gw1[:, :H]^T + c1 -> relu -> g_h1a     (routed)
// MODE 3: h1a @ gw2^T + gb2 -> sigmoid mix -> g_hmid      (routed)
// MODE 4: hmid @ fw1^T + fb1 -> relu -> g_h1b             (routed)
// MODE 5: h1b @ fw2^T + fb2 + x -> g_y                    (routed)
#define PITCH  40
#define AHO    0
#define ALO    (128 * PITCH)
#define BHO    (256 * PITCH)
#define BLO    (512 * PITCH)
#define SSE    (768 * PITCH)            // stage elems = 61440 B
#define CP2    132
#define SMEM_DYN (2 * SSE * 2 + 1024)

template <int MODE>
__global__ void __launch_bounds__(256, 1)
mgemm_k(const float* __restrict__ W, const float* __restrict__ Bias,
        const float* __restrict__ xin, const float* __restrict__ tein,
        long wstride) {
  constexpr int N = (MODE == 0) ? R1N : (MODE == 2 || MODE == 4) ? ID : HD;
  constexpr int K = (MODE == 0) ? XTK : (MODE == 1) ? R1N
                   : (MODE == 3 || MODE == 5) ? ID : HD;
  constexpr int KT = K >> 5;

  const int e = (MODE >= 2) ? blockIdx.z : 0;
  const int mcount = (MODE >= 2) ? g_cnt[e] : NTOK;
  const int moff = (MODE >= 2) ? g_off[e] : 0;
  const int m0 = blockIdx.y * 128;
  if (m0 >= mcount) return;
  const int n0 = blockIdx.x * 256;

  extern __shared__ char dsm[];
  char* dynp = (char*)(((uintptr_t)dsm + 1023) & ~(uintptr_t)1023);
  __nv_bfloat16* smb = (__nv_bfloat16*)dynp;
  float* csm = (float*)dynp;

  const int tid = threadIdx.x;
  const int wid = tid >> 5;
  const int lrow = tid >> 1;
  const int colb = (tid & 1) << 4;

  // ---- fp32 global row pointers ----
  int am = m0 + lrow;
  if (am >= mcount) am = mcount - 1;
  const float* arow;
  const float* tadj = nullptr;
  if (MODE == 0) {
    arow = xin + (size_t)am * HD;
    tadj = tein + (size_t)am * AD - HD;
  } else if (MODE == 1) {
    arow = g_rh1 + (size_t)am * R1N;
  } else {
    const int aslot = moff + am;
    if (MODE == 2)      arow = xin + (size_t)g_tok_of_slot[aslot] * HD;
    else if (MODE == 3) arow = g_h1a + (size_t)aslot * ID;
    else if (MODE == 4) arow = g_hmid + (size_t)aslot * HD;
    else                arow = g_h1b + (size_t)aslot * ID;
  }
  const float* brow0 = W + ((size_t)e * N + n0 + lrow) * (size_t)wstride;
  const float* brow1 = brow0 + (size_t)128 * wstride;

  // half-chunk prefetch: 8 columns (2 float4) per matrix -> 24 live regs
  float4 ar[2], br0[2], br1[2];

#define LOADR_H(kbase, h) do { \
  int k0_ = (kbase) + colb + (h) * 8; \
  const float* ab_ = (MODE == 0 && k0_ >= HD) ? tadj : arow; \
  ar[0]  = *(const float4*)(ab_   + k0_); \
  ar[1]  = *(const float4*)(ab_   + k0_ + 4); \
  br0[0] = *(const float4*)(brow0 + k0_); \
  br0[1] = *(const float4*)(brow0 + k0_ + 4); \
  br1[0] = *(const float4*)(brow1 + k0_); \
  br1[1] = *(const float4*)(brow1 + k0_ + 4); \
} while (0)

#define SPLIT8(srcp, dsth, dstl) do { \
  const float* f_ = (const float*)(srcp); \
  _Pragma("unroll") \
  for (int i = 0; i < 8; i += 2) { \
    __nv_bfloat16 h0, l0, h1, l1; \
    split2(f_[i], h0, l0); split2(f_[i + 1], h1, l1); \
    *(__nv_bfloat162*)((dsth) + i) = __nv_bfloat162(h0, h1); \
    *(__nv_bfloat162*)((dstl) + i) = __nv_bfloat162(l0, l1); \
  } \
} while (0)

#define STORES_H(stage, h) do { \
  __nv_bfloat16* s_ = smb + (stage) * SSE; \
  const int off_ = lrow * PITCH + colb + (h) * 8; \
  SPLIT8(ar, s_ + AHO + off_, s_ + ALO + off_); \
  __nv_bfloat16* b0_ = s_ + BHO + off_; \
  SPLIT8(br0, b0_, b0_ + (BLO - BHO)); \
  __nv_bfloat16* b1_ = s_ + BHO + 128 * PITCH + off_; \
  SPLIT8(br1, b1_, b1_ + (BLO - BHO)); \
} while (0)

  // ---- wmma tiling: 8 warps = 2(m) x 4(n); warp tile 64m x 64n ----
  const int wm = wid & 1;
  const int wn = wid >> 1;

  wmma::fragment<wmma::accumulator, 16, 16, 16, float> cf[4][4];
#pragma unroll
  for (int mt = 0; mt < 4; mt++)
#pragma unroll
    for (int nt = 0; nt < 4; nt++) wmma::fill_fragment(cf[mt][nt], 0.f);

  LOADR_H(0, 0); STORES_H(0, 0);
  LOADR_H(0, 1); STORES_H(0, 1);
  __syncthreads();

  for (int c = 0; c < KT; c++) {
    const bool pre = (c + 1 < KT);
    const int nxt = (c + 1) & 1;
    if (pre) LOADR_H((c + 1) << 5, 0);   // LDG half0; covered by MMA ks=0
    const __nv_bfloat16* sb = smb + (c & 1) * SSE;
#pragma unroll
    for (int ks = 0; ks < 2; ks++) {
      wmma::fragment<wmma::matrix_b, 16, 16, 16, __nv_bfloat16, wmma::col_major> bh[4], bl[4];
#pragma unroll
      for (int nt = 0; nt < 4; nt++) {
        const int bo = (wn * 64 + nt * 16) * PITCH + ks * 16;
        wmma::load_matrix_sync(bh[nt], sb + BHO + bo, PITCH);
        wmma::load_matrix_sync(bl[nt], sb + BLO + bo, PITCH);
      }
#pragma unroll
      for (int mt = 0; mt < 4; mt++) {
        const int ao = (wm * 64 + mt * 16) * PITCH + ks * 16;
        wmma::fragment<wmma::matrix_a, 16, 16, 16, __nv_bfloat16, wmma::row_major> ah, al;
        wmma::load_matrix_sync(ah, sb + AHO + ao, PITCH);
        wmma::load_matrix_sync(al, sb + ALO + ao, PITCH);
#pragma unroll
        for (int nt = 0; nt < 4; nt++) {
          wmma::mma_sync(cf[mt][nt], ah, bh[nt], cf[mt][nt]);
          wmma::mma_sync(cf[mt][nt], al, bh[nt], cf[mt][nt]);
          wmma::mma_sync(cf[mt][nt], ah, bl[nt], cf[mt][nt]);
        }
      }
      if (pre && ks == 0) {
        STORES_H(nxt, 0);                // retire half0 regs
        LOADR_H((c + 1) << 5, 1);        // LDG half1; covered by MMA ks=1
      }
    }
    if (pre) STORES_H(nxt, 1);
    __syncthreads();
  }

  // ---- two-pass epilogue: 128 columns at a time through fp32 smem ----
  const float* bias;
  if (MODE <= 1)      bias = Bias;
  else if (MODE == 2) bias = g_c1 + e * ID;
  else if (MODE == 3) bias = Bias + (size_t)e * HD;
  else if (MODE == 4) bias = Bias + (size_t)e * ID;
  else                bias = Bias + (size_t)e * HD;

  const int r = tid >> 1;
  const int ch = tid & 1;
  const int mi = m0 + r;
  const bool valid = (mi < mcount);
  const int slot = moff + (valid ? mi : 0);
  const int tok = (MODE >= 2) ? g_tok_of_slot[slot] : mi;
  const long orow = (MODE >= 2) ? (long)slot : (long)mi;

#pragma unroll
  for (int hf = 0; hf < 2; hf++) {
    if ((wn >> 1) == hf) {
      const int wnl = wn & 1;
#pragma unroll
      for (int mt = 0; mt < 4; mt++)
#pragma unroll
        for (int nt = 0; nt < 4; nt++)
          wmma::store_matrix_sync(csm + (wm * 64 + mt * 16) * CP2 + wnl * 64 + nt * 16,
                                  cf[mt][nt], CP2, wmma::mem_row_major);
    }
    __syncthreads();
    if (valid) {
      const float* crow = csm + r * CP2 + ch * 64;
      const int nb = n0 + hf * 128 + ch * 64;
#pragma unroll
      for (int j = 0; j < 64; j++) {
        const int n = nb + j;
        float v = crow[j] + bias[n];
        if (MODE == 0) {
          g_rh1[orow * R1N + n] = fmaxf(v, 0.f);
        } else if (MODE == 1) {
          g_rh2[orow * HD + n] = fmaxf(v, 0.f);
        } else if (MODE == 2) {
          g_h1a[orow * ID + n] = fmaxf(v, 0.f);
        } else if (MODE == 3) {
          float g = 1.f / (1.f + expf(-v));
          float xv = xin[(size_t)tok * HD + n];
          float apv = g_ap[e * HD + n];
          g_hmid[orow * HD + n] = xv * g + apv * (1.f - g);
        } else if (MODE == 4) {
          g_h1b[orow * ID + n] = fmaxf(v, 0.f);
        } else {
          g_y[orow * HD + n] = v + xin[(size_t)tok * HD + n];
        }
      }
    }
    if (hf == 0) __syncthreads();
  }
}

// ================= router head / routing / LN / combine / loss =================
__global__ void router_head_k(const float* __restrict__ te,
                              const float* __restrict__ r_attr,
                              const float* __restrict__ r_w,
                              const float* __restrict__ r_b) {
  int t = blockIdx.x;
  int tid = threadIdx.x;
  const float* hrow = g_rh2 + (size_t)t * HD;
  float pe[NE];
#pragma unroll
  for (int e = 0; e < NE; e++) pe[e] = 0.f;
  for (int k = tid; k < HD; k += 256) {
    float hv = hrow[k];
#pragma unroll
    for (int e = 0; e < NE; e++) pe[e] = fmaf(hv, r_w[e * HD + k], pe[e]);
  }
#pragma unroll
  for (int e = 0; e < NE; e++)
    for (int o = 16; o > 0; o >>= 1) pe[e] += __shfl_xor_sync(0xffffffffu, pe[e], o);
  __shared__ float sw[NE][8];
  int w = tid >> 5;
  if ((tid & 31) == 0)
#pragma unroll
    for (int e = 0; e < NE; e++) sw[e][w] = pe[e];
  __syncthreads();
  if (tid == 0) {
    float lg[NE];
    float mx = -1e30f;
    for (int e = 0; e < NE; e++) {
      float s = 0.f;
      for (int i = 0; i < 8; i++) s += sw[e][i];
      s += r_b[e];
      lg[e] = s;
      if (s > mx) mx = s;
    }
    float se = 0.f;
    for (int e = 0; e < NE; e++) { lg[e] = expf(lg[e] - mx); se += lg[e]; }
    float inv = 1.f / se;

    float attr[NE];
    for (int e = 0; e < NE; e++) attr[e] = 0.f;
    const float* tr = te + (size_t)t * AD;
    for (int n = 0; n < 4; n++) {
      float sc[NE];
      for (int e = 0; e < NE; e++) sc[e] = 0.f;
      for (int d = 0; d < 64; d++) {
        float tv = tr[n * 64 + d];
#pragma unroll
        for (int e = 0; e < NE; e++) sc[e] = fmaf(tv, r_attr[d * NE + e], sc[e]);
      }
      float m2 = -1e30f;
      for (int e = 0; e < NE; e++) if (sc[e] > m2) m2 = sc[e];
      float ss = 0.f;
      for (int e = 0; e < NE; e++) { sc[e] = expf(sc[e] - m2); ss += sc[e]; }
      float rr = 0.25f / ss;
      for (int e = 0; e < NE; e++) attr[e] += sc[e] * rr;
    }

    float p[NE];
    for (int e = 0; e < NE; e++) p[e] = lg[e] * inv * attr[e];
    int i0 = 0;
    for (int e = 1; e < NE; e++) if (p[e] > p[i0]) i0 = e;
    int i1 = (i0 == 0) ? 1 : 0;
    for (int e = 0; e < NE; e++) if (e != i0 && p[e] > p[i1]) i1 = e;

    for (int e = 0; e < NE; e++)
      g_probs[t * NE + e] = (e == i0 || e == i1) ? p[e] : 0.f;
    float p0 = p[i0], p1 = p[i1];
    g_ent[t] = p0 * logf(p0 + 1e-8f) + p1 * logf(p1 + 1e-8f);
    int elo = i0 < i1 ? i0 : i1;
    int ehi = i0 < i1 ? i1 : i0;
    g_topk[2 * t] = elo;
    g_topk[2 * t + 1] = ehi;
    atomicAdd(&g_cnt[elo], 1);
    atomicAdd(&g_cnt[ehi], 1);
  }
}

__global__ void offsets_k() {
  if (threadIdx.x == 0) {
    int o = 0;
    for (int e = 0; e < NE; e++) { g_off[e] = o; o += g_cnt[e]; }
  }
}

__global__ void assign_k() {
  int t = blockIdx.x * blockDim.x + threadIdx.x;
  if (t >= NTOK) return;
#pragma unroll
  for (int k = 0; k < 2; k++) {
    int e = g_topk[2 * t + k];
    int slot = g_off[e] + atomicAdd(&g_cursor[e], 1);
    g_tok_of_slot[slot] = t;
    g_expert_of_slot[slot] = e;
    g_slot_of_tok[2 * t + k] = slot;
  }
}

__global__ void ln_k(const float* __restrict__ lng, const float* __restrict__ lnb) {
  int s = blockIdx.x;
  int e = g_expert_of_slot[s];
  float* row = g_y + (size_t)s * HD;
  int tid = threadIdx.x;
  float4 v = *(const float4*)(row + tid * 4);
  float sum = v.x + v.y + v.z + v.w;
  float sq = v.x * v.x + v.y * v.y + v.z * v.z + v.w * v.w;
  for (int o = 16; o > 0; o >>= 1) {
    sum += __shfl_xor_sync(0xffffffffu, sum, o);
    sq += __shfl_xor_sync(0xffffffffu, sq, o);
  }
  __shared__ float s1[8], s2[8];
  int w = tid >> 5;
  if ((tid & 31) == 0) { s1[w] = sum; s2[w] = sq; }
  __syncthreads();
  float ts = 0.f, tq = 0.f;
#pragma unroll
  for (int i = 0; i < 8; i++) { ts += s1[i]; tq += s2[i]; }
  float mu = ts * (1.f / HD);
  float var = tq * (1.f / HD) - mu * mu;
  float rstd = rsqrtf(var + 1e-5f);
  const float4 g4 = *(const float4*)(lng + e * HD + tid * 4);
  const float4 b4 = *(const float4*)(lnb + e * HD + tid * 4);
  float4 o;
  o.x = (v.x - mu) * rstd * g4.x + b4.x;
  o.y = (v.y - mu) * rstd * g4.y + b4.y;
  o.z = (v.z - mu) * rstd * g4.z + b4.z;
  o.w = (v.w - mu) * rstd * g4.w + b4.w;
  *(float4*)(row + tid * 4) = o;
}

__global__ void combine_k(float* __restrict__ out) {
  int t = blockIdx.x;
  int tid = threadIdx.x;
  int s0 = g_slot_of_tok[2 * t], s1 = g_slot_of_tok[2 * t + 1];
  int e0 = g_topk[2 * t], e1 = g_topk[2 * t + 1];
  float p0 = g_probs[t * NE + e0], p1 = g_probs[t * NE + e1];
  const float4 y0 = *(const float4*)(g_y + (size_t)s0 * HD + tid * 4);
  const float4 y1 = *(const float4*)(g_y + (size_t)s1 * HD + tid * 4);
  float4 o;
  o.x = p0 * y0.x + p1 * y1.x;
  o.y = p0 * y0.y + p1 * y1.y;
  o.z = p0 * y0.z + p1 * y1.z;
  o.w = p0 * y0.w + p1 * y1.w;
  *(float4*)(out + (size_t)t * HD + tid * 4) = o;
}

__global__ void loss_k(float* __restrict__ out, int out_size) {
  __shared__ float red[256];
  float s = 0.f;
  for (int i = threadIdx.x; i < NTOK; i += 256) s += g_ent[i];
  red[threadIdx.x] = s;
  __syncthreads();
  for (int o = 128; o > 0; o >>= 1) {
    if (threadIdx.x < o) red[threadIdx.x] += red[threadIdx.x + o];
    __syncthreads();
  }
  if (threadIdx.x == 0) {
    float loss = -red[0] / (float)NTOK;
    for (int i = NTOK * HD; i < out_size; i++) out[i] = loss;
  }
}

// ================= launch =================
extern "C" void kernel_launch(void* const* d_in, const int* in_sizes, int n_in,
                              void* d_out, int out_size) {
  const float* x           = (const float*)d_in[0];
  const float* te          = (const float*)d_in[1];
  const float* attr_emb    = (const float*)d_in[2];
  const float* attr_proj_w = (const float*)d_in[3];
  const float* attr_proj_b = (const float*)d_in[4];
  const float* gate_w1     = (const float*)d_in[5];
  const float* gate_b1     = (const float*)d_in[6];
  const float* gate_w2     = (const float*)d_in[7];
  const float* gate_b2     = (const float*)d_in[8];
  const float* fc_w1       = (const float*)d_in[9];
  const float* fc_b1       = (const float*)d_in[10];
  const float* fc_w2       = (const float*)d_in[11];
  const float* fc_b2       = (const float*)d_in[12];
  const float* ln_g        = (const float*)d_in[13];
  const float* ln_b        = (const float*)d_in[14];
  const float* r_attr      = (const float*)d_in[15];
  const float* r_in_w      = (const float*)d_in[16];
  const float* r_in_b      = (const float*)d_in[17];
  const float* r_mid_w     = (const float*)d_in[18];
  const float* r_mid_b     = (const float*)d_in[19];
  const float* r_w         = (const float*)d_in[20];
  const float* r_b         = (const float*)d_in[21];
  float* out = (float*)d_out;

  cudaFuncSetAttribute(mgemm_k<0>, cudaFuncAttributeMaxDynamicSharedMemorySize, SMEM_DYN);
  cudaFuncSetAttribute(mgemm_k<1>, cudaFuncAttributeMaxDynamicSharedMemorySize, SMEM_DYN);
  cudaFuncSetAttribute(mgemm_k<2>, cudaFuncAttributeMaxDynamicSharedMemorySize, SMEM_DYN);
  cudaFuncSetAttribute(mgemm_k<3>, cudaFuncAttributeMaxDynamicSharedMemorySize, SMEM_DYN);
  cudaFuncSetAttribute(mgemm_k<4>, cudaFuncAttributeMaxDynamicSharedMemorySize, SMEM_DYN);
  cudaFuncSetAttribute(mgemm_k<5>, cudaFuncAttributeMaxDynamicSharedMemorySize, SMEM_DYN);

  reset_k<<<1, 32>>>();
  ap_k<<<(NE * HD + 255) / 256, 256>>>(attr_emb, attr_proj_w, attr_proj_b);
  c1_k<<<(NE * ID + 255) / 256, 256>>>(gate_w1, gate_b1);

  // router MLP — bf16x3 wmma (head / top-k stays exact fp32)
  mgemm_k<0><<<dim3(R1N / 256, NTOK / 128, 1), 256, SMEM_DYN>>>(r_in_w, r_in_b, x, te, XTK);
  mgemm_k<1><<<dim3(HD / 256, NTOK / 128, 1), 256, SMEM_DYN>>>(r_mid_w, r_mid_b, nullptr, nullptr, R1N);
  router_head_k<<<NTOK, 256>>>(te, r_attr, r_w, r_b);
  offsets_k<<<1, 32>>>();
  assign_k<<<NTOK / 256, 256>>>();

  // expert FFNs — bf16x3 wmma, 128x256 tiles
  mgemm_k<2><<<dim3(ID / 256, NTOK / 128, NE), 256, SMEM_DYN>>>(gate_w1, gate_b1, x, nullptr, 2 * HD);
  mgemm_k<3><<<dim3(HD / 256, NTOK / 128, NE), 256, SMEM_DYN>>>(gate_w2, gate_b2, x, nullptr, ID);
  mgemm_k<4><<<dim3(ID / 256, NTOK / 128, NE), 256, SMEM_DYN>>>(fc_w1, fc_b1, x, nullptr, HD);
  mgemm_k<5><<<dim3(HD / 256, NTOK / 128, NE), 256, SMEM_DYN>>>(fc_w2, fc_b2, x, nullptr, ID);

  ln_k<<<NSLOT, 256>>>(ln_g, ln_b);
  combine_k<<<NTOK, 256>>>(out);
  loss_k<<<1, 256>>>(out, out_size);
}